// round 14
// baseline (speedup 1.0000x reference)
#include <cuda_runtime.h>
#include <cstdint>

#define NB   8
#define CIN  256
#define TT   1024
#define HDS  8
#define DQK  64
#define DV   32
#define OCH  256

// Scratch (allocation-free rule: __device__ globals)
__device__ float g_q[NB * HDS * DQK * TT];   // [n][h][d][t], tf32-rounded
__device__ float g_k[NB * HDS * DQK * TT];   // [n][h][d][t], tf32-rounded
__device__ float g_v[NB * HDS * DV  * TT];   // [n][h][dv][t], tf32-rounded
__device__ float g_ao[NB * OCH * TT];        // [n][c=h*32+dv][t], tf32-rounded
__device__ float g_x[NB * CIN * TT];         // tf32-rounded input
__device__ float g_w[1280 * CIN];            // tf32-rounded [Wq;Wkv]
__device__ float g_wo[OCH * OCH];            // tf32-rounded Wo

// ---------------------------------------------------------------------------
// tf32 helpers
// ---------------------------------------------------------------------------
__device__ __forceinline__ uint32_t f2tf(float f) {
    uint32_t u;
    asm("cvt.rna.tf32.f32 %0, %1;" : "=r"(u) : "f"(f));
    return u;
}
__device__ __forceinline__ float f2tf_f(float f) {
    return __uint_as_float(f2tf(f));
}

// D(16x8) += A(16x8,row) * B(8x8,col), tf32 in, f32 accum
__device__ __forceinline__ void mma8(float* d, const uint32_t* a,
                                     uint32_t b0, uint32_t b1) {
    asm volatile(
        "mma.sync.aligned.m16n8k8.row.col.f32.tf32.tf32.f32 "
        "{%0,%1,%2,%3}, {%4,%5,%6,%7}, {%8,%9}, {%0,%1,%2,%3};\n"
        : "+f"(d[0]), "+f"(d[1]), "+f"(d[2]), "+f"(d[3])
        : "r"(a[0]), "r"(a[1]), "r"(a[2]), "r"(a[3]), "r"(b0), "r"(b1));
}

__device__ __forceinline__ uint32_t s2u(const void* p) {
    return (uint32_t)__cvta_generic_to_shared(p);
}
__device__ __forceinline__ void cpa16(uint32_t dst, const void* src) {
    asm volatile("cp.async.cg.shared.global [%0], [%1], 16;\n"
                 :: "r"(dst), "l"(src));
}
__device__ __forceinline__ void cpa_commit() {
    asm volatile("cp.async.commit_group;\n");
}
__device__ __forceinline__ void cpa_wait0() {
    asm volatile("cp.async.wait_group 0;\n");
}
__device__ __forceinline__ void cpa_wait1() {
    asm volatile("cp.async.wait_group 1;\n");
}

// ---------------------------------------------------------------------------
// Kernel 0: tf32 pre-rounding pass (x, [Wq;Wkv], Wo), float4 grid-stride.
// ---------------------------------------------------------------------------
#define NX4 (NB * CIN * TT / 4)       // 524288
#define NW4 (1280 * CIN / 4)          // 81920
#define NWO4 (OCH * OCH / 4)          // 16384
__global__ __launch_bounds__(256) void round_pre_kernel(
    const float* __restrict__ x, const float* __restrict__ Wq,
    const float* __restrict__ Wkv, const float* __restrict__ Wo)
{
    const int total = NX4 + NW4 + NWO4;
    for (int i = blockIdx.x * blockDim.x + threadIdx.x; i < total;
         i += gridDim.x * blockDim.x) {
        float4 v; float4* dst;
        if (i < NX4) {
            v = ((const float4*)x)[i];
            dst = (float4*)g_x + i;
        } else if (i < NX4 + NW4) {
            int j = i - NX4;
            const int wq4 = 512 * CIN / 4;
            v = (j < wq4) ? ((const float4*)Wq)[j] : ((const float4*)Wkv)[j - wq4];
            dst = (float4*)g_w + j;
        } else {
            int j = i - NX4 - NW4;
            v = ((const float4*)Wo)[j];
            dst = (float4*)g_wo + j;
        }
        float4 r;
        r.x = f2tf_f(v.x); r.y = f2tf_f(v.y); r.z = f2tf_f(v.z); r.w = f2tf_f(v.w);
        *dst = r;
    }
}

// ---------------------------------------------------------------------------
// Kernel 1: fused QKV projection, 3-stage cp.async ring, 1 barrier/stage.
// 128o x 128t tile, K=256 in 8 stages of 32.
// dyn smem: 3 x (sA[128*36] + sB[32*136]) = 107520 B (2 CTA/SM)
// grid: (T/128, 1280/128, NB). Outputs tf32-rounded.
// ---------------------------------------------------------------------------
#define GA_W 36
#define GB_W 136
#define GA_BUF (128 * GA_W)
#define GB_BUF (32 * GB_W)
#define GSTAGE (GA_BUF + GB_BUF)
#define QKV_SMEM_BYTES (3 * GSTAGE * 4)

__device__ __forceinline__ void qkv_fill_stage(
    uint32_t* sA, uint32_t* sB, const float* __restrict__ wsrc,
    const float* __restrict__ xsrc, int k0, int tid)
{
#pragma unroll
    for (int u = 0; u < 4; u++) {
        int idx = tid + u * 256;              // 1024: o(128) x kq(8)
        int o = idx >> 3, kq = idx & 7;
        cpa16(s2u(&sA[o * GA_W + kq * 4]), wsrc + (size_t)o * CIN + k0 + kq * 4);
    }
#pragma unroll
    for (int u = 0; u < 4; u++) {
        int idx = tid + u * 256;              // 1024: k(32) x tq(32)
        int k = idx >> 5, tq = idx & 31;
        cpa16(s2u(&sB[k * GB_W + tq * 4]), xsrc + (size_t)(k0 + k) * TT + tq * 4);
    }
    cpa_commit();
}

__global__ __launch_bounds__(256, 2) void qkv_kernel(
    const float* __restrict__ bq, const float* __restrict__ bkv)
{
    extern __shared__ uint32_t gsm[];
    const int n  = blockIdx.z;
    const int o0 = blockIdx.y * 128;
    const int t0 = blockIdx.x * 128;
    const int tid = threadIdx.x;
    const int lane = tid & 31, wid = tid >> 5;
    const int wo = wid >> 1, wt = wid & 1;
    const int lr = lane >> 2, lc = lane & 3;

    const float* __restrict__ wsrc = g_w + (size_t)o0 * CIN;
    const float* __restrict__ xsrc = g_x + (size_t)n * CIN * TT + t0;

    float d[2][8][4];
#pragma unroll
    for (int mi = 0; mi < 2; mi++)
#pragma unroll
        for (int j = 0; j < 8; j++)
#pragma unroll
            for (int q = 0; q < 4; q++) d[mi][j][q] = 0.f;

    // prologue: stages 0 and 1
    qkv_fill_stage(gsm, gsm + GA_BUF, wsrc, xsrc, 0, tid);
    qkv_fill_stage(gsm + GSTAGE, gsm + GSTAGE + GA_BUF, wsrc, xsrc, 32, tid);

#pragma unroll
    for (int st = 0; st < 8; st++) {
        if (st < 7) cpa_wait1(); else cpa_wait0();   // fill(st) complete
        __syncthreads();                              // all warps past MMA(st-1)
        if (st + 2 < 8) {
            uint32_t* nb = gsm + ((st + 2) % 3) * GSTAGE;
            qkv_fill_stage(nb, nb + GA_BUF, wsrc, xsrc, (st + 2) * 32, tid);
        }
        uint32_t* sA = gsm + (st % 3) * GSTAGE;
        uint32_t* sB = sA + GA_BUF;

#pragma unroll
        for (int kk = 0; kk < 4; kk++) {
            const int kc = kk * 8;
            uint32_t a[2][4];
#pragma unroll
            for (int mi = 0; mi < 2; mi++) {
                int row = wo * 32 + mi * 16 + lr;
                a[mi][0] = sA[row * GA_W + kc + lc];
                a[mi][1] = sA[(row + 8) * GA_W + kc + lc];
                a[mi][2] = sA[row * GA_W + kc + 4 + lc];
                a[mi][3] = sA[(row + 8) * GA_W + kc + 4 + lc];
            }
#pragma unroll
            for (int j = 0; j < 8; j++) {
                int col = wt * 64 + j * 8 + lr;
                uint32_t b0 = sB[(kc + lc) * GB_W + col];
                uint32_t b1 = sB[(kc + 4 + lc) * GB_W + col];
                mma8(d[0][j], a[0], b0, b1);
                mma8(d[1][j], a[1], b0, b1);
            }
        }
    }

    // epilogue: route rows to g_q / g_k / g_v, tf32-rounded
#pragma unroll
    for (int mi = 0; mi < 2; mi++) {
#pragma unroll
        for (int half = 0; half < 2; half++) {
            int o = o0 + wo * 32 + mi * 16 + half * 8 + lr;
            float bias;
            float* dst;
            if (o < 512) {
                int h = o >> 6, dd = o & 63;
                bias = bq[o];
                dst = g_q + (((size_t)n * HDS + h) * DQK + dd) * TT;
            } else if (o < 1024) {
                int oo = o - 512, h = oo >> 6, dd = oo & 63;
                bias = bkv[o - 512];
                dst = g_k + (((size_t)n * HDS + h) * DQK + dd) * TT;
            } else {
                int oo = o - 1024, h = oo >> 5, dd = oo & 31;
                bias = bkv[o - 512];
                dst = g_v + (((size_t)n * HDS + h) * DV + dd) * TT;
            }
#pragma unroll
            for (int j = 0; j < 8; j++) {
                int t = t0 + wt * 64 + j * 8 + lc * 2;
                dst[t]     = f2tf_f(d[mi][j][half * 2 + 0] + bias);
                dst[t + 1] = f2tf_f(d[mi][j][half * 2 + 1] + bias);
            }
        }
    }
}

// ---------------------------------------------------------------------------
// Kernel 2: flash attention (unchanged from R13 pass).
// ---------------------------------------------------------------------------
#define SK_STRIDE 72
#define SV_STRIDE 68
#define SP_STRIDE 68
#define SK_BUF (64 * SK_STRIDE)
#define SV_BUF (32 * SV_STRIDE)
#define ATTN_SMEM_WORDS (2 * SK_BUF + 2 * SV_BUF + 128 * SP_STRIDE)

__global__ __launch_bounds__(256, 2) void attn_kernel()
{
    extern __shared__ uint32_t dynsmem[];
    uint32_t* sK = dynsmem;
    uint32_t* sV = dynsmem + 2 * SK_BUF;
    uint32_t* sP = sV + 2 * SV_BUF;

    const int nh = blockIdx.y;
    const int qb = (gridDim.x - 1) - blockIdx.x;
    const int tid = threadIdx.x;
    const int lane = tid & 31, w = tid >> 5;
    const int lr = lane >> 2, lc = lane & 3;
    const float scale = 0.125f;

    const float* __restrict__ qp = g_q + (size_t)nh * DQK * TT;
    const float* __restrict__ kp = g_k + (size_t)nh * DQK * TT;
    const float* __restrict__ vp = g_v + (size_t)nh * DV * TT;

    const int t0 = qb * 128;
    const int t0w = t0 + w * 16;
    const int nkb = 2 * qb + 2;

    const uint32_t* __restrict__ qpu = (const uint32_t*)qp;
    uint32_t qfr[8][4];
#pragma unroll
    for (int kd = 0; kd < 8; kd++) {
        int d0 = kd * 8 + lc;
        qfr[kd][0] = qpu[(size_t)d0 * TT + t0w + lr];
        qfr[kd][1] = qpu[(size_t)d0 * TT + t0w + lr + 8];
        qfr[kd][2] = qpu[(size_t)(d0 + 4) * TT + t0w + lr];
        qfr[kd][3] = qpu[(size_t)(d0 + 4) * TT + t0w + lr + 8];
    }

    {
        const int s0 = 0;
#pragma unroll
        for (int u = 0; u < 4; u++) {
            int idx = tid + u * 256;
            int dd = idx >> 4, sg = idx & 15;
            cpa16(s2u(&sK[dd * SK_STRIDE + sg * 4]), kp + (size_t)dd * TT + s0 + sg * 4);
        }
#pragma unroll
        for (int u = 0; u < 2; u++) {
            int idx = tid + u * 256;
            int dd = idx >> 4, sg = idx & 15;
            cpa16(s2u(&sV[dd * SV_STRIDE + sg * 4]), vp + (size_t)dd * TT + s0 + sg * 4);
        }
        cpa_commit();
    }

    float m0 = -1e30f, m1 = -1e30f, l0 = 0.f, l1 = 0.f;
    float o_[4][4];
#pragma unroll
    for (int j = 0; j < 4; j++)
#pragma unroll
        for (int q = 0; q < 4; q++) o_[j][q] = 0.f;

    for (int kb = 0; kb < nkb; kb++) {
        cpa_wait0();
        __syncthreads();

        if (kb + 1 < nkb) {
            const int sn = (kb + 1) * 64;
            uint32_t* sKn = sK + ((kb + 1) & 1) * SK_BUF;
            uint32_t* sVn = sV + ((kb + 1) & 1) * SV_BUF;
#pragma unroll
            for (int u = 0; u < 4; u++) {
                int idx = tid + u * 256;
                int dd = idx >> 4, sg = idx & 15;
                cpa16(s2u(&sKn[dd * SK_STRIDE + sg * 4]), kp + (size_t)dd * TT + sn + sg * 4);
            }
#pragma unroll
            for (int u = 0; u < 2; u++) {
                int idx = tid + u * 256;
                int dd = idx >> 4, sg = idx & 15;
                cpa16(s2u(&sVn[dd * SV_STRIDE + sg * 4]), vp + (size_t)dd * TT + sn + sg * 4);
            }
            cpa_commit();
        }

        const int s0 = kb * 64;
        const bool active = (s0 <= t0w + 15);
        if (active) {
            const uint32_t* sKb = sK + (kb & 1) * SK_BUF;
            const uint32_t* sVb = sV + (kb & 1) * SV_BUF;

            float s[8][4];
#pragma unroll
            for (int j = 0; j < 8; j++)
#pragma unroll
                for (int q = 0; q < 4; q++) s[j][q] = 0.f;

#pragma unroll
            for (int kd = 0; kd < 8; kd++) {
                const int kc = kd * 8;
#pragma unroll
                for (int j = 0; j < 8; j++) {
                    uint32_t b0 = sKb[(kc + lc) * SK_STRIDE + j * 8 + lr];
                    uint32_t b1 = sKb[(kc + 4 + lc) * SK_STRIDE + j * 8 + lr];
                    mma8(s[j], qfr[kd], b0, b1);
                }
            }

            const int tg0 = t0w + lr, tg1 = tg0 + 8;
            const bool need_mask = (s0 + 63 > t0w);
#pragma unroll
            for (int j = 0; j < 8; j++) {
                int sg = s0 + j * 8 + lc * 2;
                s[j][0] *= scale; s[j][1] *= scale; s[j][2] *= scale; s[j][3] *= scale;
                if (need_mask) {
                    if (sg     > tg0) s[j][0] = -1e30f;
                    if (sg + 1 > tg0) s[j][1] = -1e30f;
                    if (sg     > tg1) s[j][2] = -1e30f;
                    if (sg + 1 > tg1) s[j][3] = -1e30f;
                }
            }

            float mn0 = -1e30f, mn1 = -1e30f;
#pragma unroll
            for (int j = 0; j < 8; j++) {
                mn0 = fmaxf(mn0, fmaxf(s[j][0], s[j][1]));
                mn1 = fmaxf(mn1, fmaxf(s[j][2], s[j][3]));
            }
            mn0 = fmaxf(mn0, __shfl_xor_sync(0xffffffffu, mn0, 1));
            mn0 = fmaxf(mn0, __shfl_xor_sync(0xffffffffu, mn0, 2));
            mn1 = fmaxf(mn1, __shfl_xor_sync(0xffffffffu, mn1, 1));
            mn1 = fmaxf(mn1, __shfl_xor_sync(0xffffffffu, mn1, 2));

            float mN0 = fmaxf(m0, mn0), mN1 = fmaxf(m1, mn1);
            float al0 = __expf(m0 - mN0), al1 = __expf(m1 - mN1);
            m0 = mN0; m1 = mN1;

            float rs0 = 0.f, rs1 = 0.f;
#pragma unroll
            for (int j = 0; j < 8; j++) {
                s[j][0] = __expf(s[j][0] - m0); rs0 += s[j][0];
                s[j][1] = __expf(s[j][1] - m0); rs0 += s[j][1];
                s[j][2] = __expf(s[j][2] - m1); rs1 += s[j][2];
                s[j][3] = __expf(s[j][3] - m1); rs1 += s[j][3];
            }
            rs0 += __shfl_xor_sync(0xffffffffu, rs0, 1);
            rs0 += __shfl_xor_sync(0xffffffffu, rs0, 2);
            rs1 += __shfl_xor_sync(0xffffffffu, rs1, 1);
            rs1 += __shfl_xor_sync(0xffffffffu, rs1, 2);
            l0 = l0 * al0 + rs0;
            l1 = l1 * al1 + rs1;

#pragma unroll
            for (int j = 0; j < 4; j++) {
                o_[j][0] *= al0; o_[j][1] *= al0;
                o_[j][2] *= al1; o_[j][3] *= al1;
            }

            {
                const int r0 = w * 16 + lr;
#pragma unroll
                for (int j = 0; j < 8; j++) {
                    int c = j * 8 + lc * 2;
                    sP[r0 * SP_STRIDE + c]           = f2tf(s[j][0]);
                    sP[r0 * SP_STRIDE + c + 1]       = f2tf(s[j][1]);
                    sP[(r0 + 8) * SP_STRIDE + c]     = f2tf(s[j][2]);
                    sP[(r0 + 8) * SP_STRIDE + c + 1] = f2tf(s[j][3]);
                }
            }
            __syncwarp();

            // sVb is [dv][s]: B element (k=s, n=dv) at sVb[dv*SV_STRIDE + s]
#pragma unroll
            for (int ksx = 0; ksx < 8; ksx++) {
                const int ks = ksx * 8;
                uint32_t a[4];
                a[0] = sP[(w * 16 + lr) * SP_STRIDE + ks + lc];
                a[1] = sP[(w * 16 + lr + 8) * SP_STRIDE + ks + lc];
                a[2] = sP[(w * 16 + lr) * SP_STRIDE + ks + 4 + lc];
                a[3] = sP[(w * 16 + lr + 8) * SP_STRIDE + ks + 4 + lc];
#pragma unroll
                for (int j = 0; j < 4; j++) {
                    uint32_t b0 = sVb[(j * 8 + lr) * SV_STRIDE + ks + lc];
                    uint32_t b1 = sVb[(j * 8 + lr) * SV_STRIDE + ks + 4 + lc];
                    mma8(o_[j], a, b0, b1);
                }
            }
        }
    }

    const int n = nh >> 3, h = nh & 7;
    float* __restrict__ aob = g_ao + ((size_t)n * OCH + h * DV) * TT;
    const float inv0 = 1.f / l0, inv1 = 1.f / l1;
    const int tg0 = t0w + lr, tg1 = tg0 + 8;
#pragma unroll
    for (int j = 0; j < 4; j++) {
        int dv = j * 8 + lc * 2;
        aob[(size_t)dv * TT + tg0]       = f2tf_f(o_[j][0] * inv0);
        aob[(size_t)(dv + 1) * TT + tg0] = f2tf_f(o_[j][1] * inv0);
        aob[(size_t)dv * TT + tg1]       = f2tf_f(o_[j][2] * inv1);
        aob[(size_t)(dv + 1) * TT + tg1] = f2tf_f(o_[j][3] * inv1);
    }
}

// ---------------------------------------------------------------------------
// Kernel 3: output projection, 64o x 128t tiles, 3-stage ring, 1 barrier/stage.
// dyn smem: 3 x (sA[64*36] + sB[32*136]) = 79872 B (2 CTA/SM)
// grid: (T/128, 256/64, NB) = 256 blocks.
// ---------------------------------------------------------------------------
#define OA_BUF (64 * GA_W)
#define OSTAGE (OA_BUF + GB_BUF)
#define OP_SMEM_BYTES (3 * OSTAGE * 4)

__device__ __forceinline__ void op_fill_stage(
    uint32_t* sA, uint32_t* sB, const float* __restrict__ wsrc,
    const float* __restrict__ xsrc, int k0, int tid)
{
#pragma unroll
    for (int u = 0; u < 2; u++) {
        int idx = tid + u * 256;              // 512: o(64) x kq(8)
        int o = idx >> 3, kq = idx & 7;
        cpa16(s2u(&sA[o * GA_W + kq * 4]), wsrc + (size_t)o * OCH + k0 + kq * 4);
    }
#pragma unroll
    for (int u = 0; u < 4; u++) {
        int idx = tid + u * 256;              // 1024: k(32) x tq(32)
        int k = idx >> 5, tq = idx & 31;
        cpa16(s2u(&sB[k * GB_W + tq * 4]), xsrc + (size_t)(k0 + k) * TT + tq * 4);
    }
    cpa_commit();
}

__global__ __launch_bounds__(256, 2) void out_proj_kernel(
    const float* __restrict__ bo, float* __restrict__ out)
{
    extern __shared__ uint32_t gsm[];
    const int n  = blockIdx.z;
    const int o0 = blockIdx.y * 64;
    const int t0 = blockIdx.x * 128;
    const int tid = threadIdx.x;
    const int lane = tid & 31, wid = tid >> 5;
    const int wo = wid >> 1, wt = wid & 1;
    const int lr = lane >> 2, lc = lane & 3;

    const float* __restrict__ wsrc = g_wo + (size_t)o0 * OCH;
    const float* __restrict__ xsrc = g_ao + (size_t)n * OCH * TT + t0;

    float d[8][4];
#pragma unroll
    for (int j = 0; j < 8; j++)
#pragma unroll
        for (int q = 0; q < 4; q++) d[j][q] = 0.f;

    op_fill_stage(gsm, gsm + OA_BUF, wsrc, xsrc, 0, tid);
    op_fill_stage(gsm + OSTAGE, gsm + OSTAGE + OA_BUF, wsrc, xsrc, 32, tid);

#pragma unroll
    for (int st = 0; st < 8; st++) {
        if (st < 7) cpa_wait1(); else cpa_wait0();
        __syncthreads();
        if (st + 2 < 8) {
            uint32_t* nb = gsm + ((st + 2) % 3) * OSTAGE;
            op_fill_stage(nb, nb + OA_BUF, wsrc, xsrc, (st + 2) * 32, tid);
        }
        uint32_t* sA = gsm + (st % 3) * OSTAGE;
        uint32_t* sB = sA + OA_BUF;

#pragma unroll
        for (int kk = 0; kk < 4; kk++) {
            const int kc = kk * 8;
            uint32_t a[4];
            int row = wo * 16 + lr;
            a[0] = sA[row * GA_W + kc + lc];
            a[1] = sA[(row + 8) * GA_W + kc + lc];
            a[2] = sA[row * GA_W + kc + 4 + lc];
            a[3] = sA[(row + 8) * GA_W + kc + 4 + lc];
#pragma unroll
            for (int j = 0; j < 8; j++) {
                int col = wt * 64 + j * 8 + lr;
                uint32_t b0 = sB[(kc + lc) * GB_W + col];
                uint32_t b1 = sB[(kc + 4 + lc) * GB_W + col];
                mma8(d[j], a, b0, b1);
            }
        }
    }

#pragma unroll
    for (int half = 0; half < 2; half++) {
        int o = o0 + wo * 16 + half * 8 + lr;
        float bias = bo[o];
        float* dst = out + ((size_t)n * OCH + o) * TT;
#pragma unroll
        for (int j = 0; j < 8; j++) {
            int t = t0 + wt * 64 + j * 8 + lc * 2;
            dst[t]     = d[j][half * 2 + 0] + bias;
            dst[t + 1] = d[j][half * 2 + 1] + bias;
        }
    }
}

// ---------------------------------------------------------------------------
extern "C" void kernel_launch(void* const* d_in, const int* in_sizes, int n_in,
                              void* d_out, int out_size)
{
    const float* x   = (const float*)d_in[0];
    const float* Wq  = (const float*)d_in[1];
    const float* bq  = (const float*)d_in[2];
    const float* Wkv = (const float*)d_in[3];
    const float* bkv = (const float*)d_in[4];
    const float* Wo  = (const float*)d_in[5];
    const float* bo  = (const float*)d_in[6];
    float* out = (float*)d_out;

    cudaFuncSetAttribute(attn_kernel,
                         cudaFuncAttributeMaxDynamicSharedMemorySize,
                         ATTN_SMEM_WORDS * 4);
    cudaFuncSetAttribute(qkv_kernel,
                         cudaFuncAttributeMaxDynamicSharedMemorySize,
                         QKV_SMEM_BYTES);
    cudaFuncSetAttribute(out_proj_kernel,
                         cudaFuncAttributeMaxDynamicSharedMemorySize,
                         OP_SMEM_BYTES);

    round_pre_kernel<<<1024, 256>>>(x, Wq, Wkv, Wo);
    qkv_kernel<<<dim3(TT / 128, 1280 / 128, NB), 256, QKV_SMEM_BYTES>>>(bq, bkv);
    attn_kernel<<<dim3(TT / 128, NB * HDS), 256, ATTN_SMEM_WORDS * 4>>>();
    out_proj_kernel<<<dim3(TT / 128, OCH / 64, NB), 256, OP_SMEM_BYTES>>>(bo, out);
}